// round 10
// baseline (speedup 1.0000x reference)
#include <cuda_runtime.h>
#include <cuda_fp16.h>
#include <cstdint>

// ============================================================
// AWQLinear via fp16 mma.sync m16n8k16. R9: persistent GEMM,
// 296 CTAs (2/SM), dynamic tile scheduler (atomic counter),
// cross-tile-continuous 3-stage cp.async ring (wait_group 1).
// y = (x/alpha) @ W_hat^T + bias, M=4096 N=11008 K=4096.
// ============================================================

#define IN_F   4096
#define OUT_F  11008
#define MROWS  4096
#define NKT    64
#define TM     128
#define TN     128
#define NTILES ((MROWS / TM) * (OUT_F / TN))    // 32*86 = 2752
#define A_KT_BYTES 16384
#define B_KT_BYTES 16384
#define STAGE_BYTES (A_KT_BYTES + B_KT_BYTES)   // 32KB
#define SMEM_BYTES (3 * STAGE_BYTES)            // 96KB (2 CTAs/SM)

#define XCHUNKS (MROWS * IN_F / 8)
#define WCHUNKS (OUT_F * IN_F / 8)
#define WBLOCKS (WCHUNKS / 256)                 // 22016
#define XBLOCKS (XCHUNKS / 256)                 // 8192

__device__ __half2 g_A[(size_t)XCHUNKS * 4];    // 32MB
__device__ __half2 g_B[(size_t)WCHUNKS * 4];    // 90MB
__device__ int g_ctr;                           // tile counter

// ---------------- helpers ----------------
__device__ __forceinline__ uint32_t smem_u32(const void* p) {
    uint32_t a;
    asm("{ .reg .u64 t; cvta.to.shared.u64 t, %1; cvt.u32.u64 %0, t; }"
        : "=r"(a) : "l"(p));
    return a;
}
__device__ __forceinline__ void cp16(uint32_t dst, const void* src) {
    asm volatile("cp.async.cg.shared.global [%0], [%1], 16;"
                 :: "r"(dst), "l"(src) : "memory");
}
#define CP_COMMIT() asm volatile("cp.async.commit_group;" ::: "memory")
#define CP_WAIT1()  asm volatile("cp.async.wait_group 1;" ::: "memory")

__device__ __forceinline__ void mma_f16(float4& d, const uint4 a,
                                        const uint32_t b0, const uint32_t b1) {
    asm("mma.sync.aligned.m16n8k16.row.col.f32.f16.f16.f32 "
        "{%0,%1,%2,%3}, {%4,%5,%6,%7}, {%8,%9}, {%0,%1,%2,%3};"
        : "+f"(d.x), "+f"(d.y), "+f"(d.z), "+f"(d.w)
        : "r"(a.x), "r"(a.y), "r"(a.z), "r"(a.w), "r"(b0), "r"(b1));
}
__device__ __forceinline__ uint32_t h2u(__half2 h) { return *(uint32_t*)&h; }

// ---------------- merged prep (also resets the tile counter) ------------
__global__ void prep_all_kernel(const float* __restrict__ x,
                                const float* __restrict__ alpha,
                                const int* __restrict__ q,
                                const float* __restrict__ sc) {
    int bid = blockIdx.x;
    if (bid == 0 && threadIdx.x == 0) g_ctr = 0;
    if (bid < WBLOCKS) {
        int j = bid * 256 + threadIdx.x;
        int blk = j >> 10, c = j & 1023;
        int th = c & 31, jp = (c >> 5) & 7, s = c >> 8;
        int nb = blk >> 6, kt = blk & 63;
        int o0 = (nb << 7) + (jp << 4) + (th >> 2);
        int k0 = (kt << 6) + (s << 4) + ((th & 3) << 1);
        int sblk = (kt << 1) + (s >> 1);
        const int* q0 = q + ((size_t)o0 << 12) + k0;
        const int* q8 = q0 + (8 << 12);
        float s0 = sc[(o0 << 7) + sblk];
        float s1 = sc[((o0 + 8) << 7) + sblk];
        int2 a0 = *(const int2*)(q0);
        int2 a2 = *(const int2*)(q0 + 8);
        int2 b0 = *(const int2*)(q8);
        int2 b2 = *(const int2*)(q8 + 8);
        uint4 o;
        o.x = h2u(__floats2half2_rn((float)(a0.x - 8) * s0, (float)(a0.y - 8) * s0));
        o.y = h2u(__floats2half2_rn((float)(a2.x - 8) * s0, (float)(a2.y - 8) * s0));
        o.z = h2u(__floats2half2_rn((float)(b0.x - 8) * s1, (float)(b0.y - 8) * s1));
        o.w = h2u(__floats2half2_rn((float)(b2.x - 8) * s1, (float)(b2.y - 8) * s1));
        *(uint4*)(g_B + (size_t)j * 4) = o;
    } else {
        int j = (bid - WBLOCKS) * 256 + threadIdx.x;
        int blk = j >> 10, c = j & 1023;
        int th = c & 31, it = (c >> 5) & 7, s = c >> 8;
        int mb = blk >> 6, kt = blk & 63;
        int row0 = (mb << 7) + (it << 4) + (th >> 2);
        int k0 = (kt << 6) + (s << 4) + ((th & 3) << 1);
        const float* x0 = x + ((size_t)row0 << 12) + k0;
        const float* x8 = x0 + (8 << 12);
        float ia0 = 1.0f / alpha[k0],     ia1 = 1.0f / alpha[k0 + 1];
        float ia8 = 1.0f / alpha[k0 + 8], ia9 = 1.0f / alpha[k0 + 9];
        float2 v00 = *(const float2*)(x0);
        float2 v10 = *(const float2*)(x8);
        float2 v08 = *(const float2*)(x0 + 8);
        float2 v18 = *(const float2*)(x8 + 8);
        uint4 o;
        o.x = h2u(__floats2half2_rn(v00.x * ia0, v00.y * ia1));
        o.y = h2u(__floats2half2_rn(v10.x * ia0, v10.y * ia1));
        o.z = h2u(__floats2half2_rn(v08.x * ia8, v08.y * ia9));
        o.w = h2u(__floats2half2_rn(v18.x * ia8, v18.y * ia9));
        *(uint4*)(g_A + (size_t)j * 4) = o;
    }
}

// ---------------- persistent GEMM ----------------
__global__ __launch_bounds__(128, 2)
void awq_gemm_kernel(const float* __restrict__ bias, float* __restrict__ out) {
    extern __shared__ char sm[];
    __shared__ int s_next;
    const uint32_t sbase = smem_u32(sm);
    int tid = threadIdx.x, wid = tid >> 5, t = tid & 31;
    int wm = wid & 1, wn = wid >> 1;

    const uint32_t cpoff = sbase + (uint32_t)tid * 16;
    auto copy_stage = [&](const char* a, const char* b, int kt, uint32_t pbase) {
        const char* srcA = a + (size_t)kt * A_KT_BYTES + tid * 16;
#pragma unroll
        for (int r = 0; r < 8; r++)
            cp16(cpoff + pbase + r * 2048, srcA + r * 2048);
        const char* srcB = b + (size_t)kt * B_KT_BYTES + tid * 16;
#pragma unroll
        for (int r = 0; r < 8; r++)
            cp16(cpoff + pbase + A_KT_BYTES + r * 2048, srcB + r * 2048);
    };

    // first tile
    if (tid == 0) s_next = atomicAdd(&g_ctr, 1);
    __syncthreads();
    int cur = s_next;
    if (cur >= NTILES) return;

    const char* gA = (const char*)g_A + (size_t)(cur & 31) * (NKT * A_KT_BYTES);
    const char* gB = (const char*)g_B + (size_t)(cur >> 5) * (NKT * B_KT_BYTES);

    copy_stage(gA, gB, 0, 0); CP_COMMIT();
    copy_stage(gA, gB, 1, STAGE_BYTES); CP_COMMIT();
    CP_WAIT1();
    __syncthreads();

    const int aoff = wm * 2048 + t * 16;
    const int boff = A_KT_BYTES + wn * 2048 + t * 16;
    const int quad = t >> 2, tq = t & 3;

    float4 acc[4][8];
#pragma unroll
    for (int i = 0; i < 4; i++)
#pragma unroll
        for (int jj = 0; jj < 8; jj++) acc[i][jj] = make_float4(0.f, 0.f, 0.f, 0.f);

    uint4 fa[2][4], fb[2][4];
    auto load_frag = [&](int bi, const char* stage, int s) {
        const char* ab = stage + s * 4096 + aoff;
        const char* bb = stage + s * 4096 + boff;
#pragma unroll
        for (int il = 0; il < 4; il++) fa[bi][il] = *(const uint4*)(ab + il * 512);
#pragma unroll
        for (int pl = 0; pl < 4; pl++) fb[bi][pl] = *(const uint4*)(bb + pl * 512);
    };
    auto do_mma = [&](int bi) {
#pragma unroll
        for (int il = 0; il < 4; il++)
#pragma unroll
            for (int jj = 0; jj < 8; jj++) {
                const uint4& bp = fb[bi][jj >> 1];
                if (jj & 1) mma_f16(acc[il][jj], fa[bi][il], bp.z, bp.w);
                else        mma_f16(acc[il][jj], fa[bi][il], bp.x, bp.y);
            }
    };

    const char* stages[3] = { sm, sm + STAGE_BYTES, sm + 2 * STAGE_BYTES };
    int p = 0;

    for (;;) {
        // grab successor tile (visible to all threads after kt=0's barrier)
        if (tid == 0) s_next = atomicAdd(&g_ctr, 1);
        int nxt = NTILES;
        const char *nA = gA, *nB = gB;

        for (int kt = 0; kt < NKT; kt++) {
            const char* stage = stages[p];
            int pn = (p + 1 == 3) ? 0 : p + 1;
            int pw = (pn + 1 == 3) ? 0 : pn + 1;
            if (kt == 1) {                       // after kt=0's barrier
                nxt = s_next;
                if (nxt < NTILES) {
                    nA = (const char*)g_A + (size_t)(nxt & 31) * (NKT * A_KT_BYTES);
                    nB = (const char*)g_B + (size_t)(nxt >> 5) * (NKT * B_KT_BYTES);
                }
            }
            if (kt + 2 < NKT)
                copy_stage(gA, gB, kt + 2, (uint32_t)(pw * STAGE_BYTES));
            else if (nxt < NTILES)               // next tile chunks 0,1
                copy_stage(nA, nB, kt + 2 - NKT, (uint32_t)(pw * STAGE_BYTES));
            CP_COMMIT();
            load_frag(0, stage, 0);
#pragma unroll
            for (int s = 0; s < 4; s++) {
                int c2 = s & 1;
                if (s < 3) load_frag(c2 ^ 1, stage, s + 1);
                do_mma(c2);
            }
            CP_WAIT1();
            __syncthreads();
            p = pn;
        }

        // epilogue for cur (copies for next tile still in flight)
        {
            int row_base = (cur & 31) * TM + wm * 64;
            int col_base = (cur >> 5) * TN + wn * 64;
#pragma unroll
            for (int il = 0; il < 4; il++) {
                int r0 = row_base + il * 16 + quad;
                float* o0 = out + (size_t)r0 * OUT_F;
                float* o1 = o0 + (size_t)8 * OUT_F;
#pragma unroll
                for (int jj = 0; jj < 8; jj++) {
                    int cc = col_base + jj * 8 + tq * 2;
                    float2 bv = *(const float2*)(bias + cc);
                    float4 v = acc[il][jj];
                    *(float2*)(o0 + cc) = make_float2(v.x + bv.x, v.y + bv.y);
                    *(float2*)(o1 + cc) = make_float2(v.z + bv.x, v.w + bv.y);
                }
            }
        }
        if (nxt >= NTILES) break;
        cur = nxt; gA = nA; gB = nB;
#pragma unroll
        for (int i = 0; i < 4; i++)
#pragma unroll
            for (int jj = 0; jj < 8; jj++) acc[i][jj] = make_float4(0.f, 0.f, 0.f, 0.f);
        // ring invariant: stage[p] already holds nxt chunk 0 (arrived),
        // chunk 1 is the single pending group — same as steady state.
    }
}

// ---------------- launch ----------------
extern "C" void kernel_launch(void* const* d_in, const int* in_sizes, int n_in,
                              void* d_out, int out_size) {
    const float* x     = (const float*)d_in[0];
    const int*   qw    = (const int*)d_in[1];
    const float* sc    = (const float*)d_in[2];
    const float* alpha = (const float*)d_in[3];
    const float* bias  = (const float*)d_in[4];
    float* out = (float*)d_out;

    cudaFuncSetAttribute(awq_gemm_kernel,
                         cudaFuncAttributeMaxDynamicSharedMemorySize, SMEM_BYTES);

    prep_all_kernel<<<WBLOCKS + XBLOCKS, 256>>>(x, alpha, qw, sc);

    awq_gemm_kernel<<<296, 128, SMEM_BYTES>>>(bias, out);
}

// round 11
// speedup vs baseline: 1.2551x; 1.2551x over previous
#include <cuda_runtime.h>
#include <cuda_fp16.h>
#include <cstdint>

// ============================================================
// AWQLinear via fp16 mma.sync m16n8k16 (same mantissa as tf32).
// y = (x/alpha) @ W_hat^T + bias, M=4096 N=11008 K=4096.
// R10 = R6 GEMM (best measured: 256x128 CTA, 8 warps, 4-stage
// cp.async WAIT1, cross-iter s0 prefetch) + merged prep kernel.
// ============================================================

#define IN_F   4096
#define OUT_F  11008
#define MROWS  4096
#define NKT    64            // K / 64
#define TM     256
#define TN     128
#define A_BLK_B32 8192       // 32KB per (mb,kt)
#define B_BLK_B32 4096       // 16KB per (nb,kt)
#define STAGE_BYTES ((A_BLK_B32 + B_BLK_B32) * 4)     // 48KB
#define SMEM_BYTES (4 * STAGE_BYTES)                  // 192KB
#define A_KT_BYTES (A_BLK_B32 * 4)
#define B_KT_BYTES (B_BLK_B32 * 4)

#define XCHUNKS (MROWS * IN_F / 8)              // 2,097,152
#define WCHUNKS (OUT_F * IN_F / 8)              // 5,636,096
#define WBLOCKS (WCHUNKS / 256)                 // 22016
#define XBLOCKS (XCHUNKS / 256)                 // 8192

__device__ __half2 g_A[(size_t)XCHUNKS * 4];    // 32MB
__device__ __half2 g_B[(size_t)WCHUNKS * 4];    // 90MB

// ---------------- helpers ----------------
__device__ __forceinline__ uint32_t smem_u32(const void* p) {
    uint32_t a;
    asm("{ .reg .u64 t; cvta.to.shared.u64 t, %1; cvt.u32.u64 %0, t; }"
        : "=r"(a) : "l"(p));
    return a;
}
__device__ __forceinline__ void cp16(uint32_t dst, const void* src) {
    asm volatile("cp.async.cg.shared.global [%0], [%1], 16;"
                 :: "r"(dst), "l"(src) : "memory");
}
#define CP_COMMIT() asm volatile("cp.async.commit_group;" ::: "memory")
#define CP_WAIT1()  asm volatile("cp.async.wait_group 1;" ::: "memory")

__device__ __forceinline__ void mma_f16(float4& d, const uint4 a,
                                        const uint32_t b0, const uint32_t b1) {
    asm("mma.sync.aligned.m16n8k16.row.col.f32.f16.f16.f32 "
        "{%0,%1,%2,%3}, {%4,%5,%6,%7}, {%8,%9}, {%0,%1,%2,%3};"
        : "+f"(d.x), "+f"(d.y), "+f"(d.z), "+f"(d.w)
        : "r"(a.x), "r"(a.y), "r"(a.z), "r"(a.w), "r"(b0), "r"(b1));
}
__device__ __forceinline__ uint32_t h2u(__half2 h) { return *(uint32_t*)&h; }

// ---------------- merged prep: 1 thread = one 16B fragment chunk --------
// W (nb,kt) blocks first (TN=128 layout), then X (mb,kt) blocks (TM=256).
__global__ void prep_all_kernel(const float* __restrict__ x,
                                const float* __restrict__ alpha,
                                const int* __restrict__ q,
                                const float* __restrict__ sc) {
    int bid = blockIdx.x;
    if (bid < WBLOCKS) {
        int j = bid * 256 + threadIdx.x;          // < WCHUNKS
        int blk = j >> 10, c = j & 1023;
        int th = c & 31, jp = (c >> 5) & 7, s = c >> 8;
        int nb = blk >> 6, kt = blk & 63;
        int o0 = (nb << 7) + (jp << 4) + (th >> 2);
        int k0 = (kt << 6) + (s << 4) + ((th & 3) << 1);
        int sblk = (kt << 1) + (s >> 1);
        const int* q0 = q + ((size_t)o0 << 12) + k0;
        const int* q8 = q0 + (8 << 12);
        float s0 = sc[(o0 << 7) + sblk];
        float s1 = sc[((o0 + 8) << 7) + sblk];
        int2 a0 = *(const int2*)(q0);
        int2 a2 = *(const int2*)(q0 + 8);
        int2 b0 = *(const int2*)(q8);
        int2 b2 = *(const int2*)(q8 + 8);
        uint4 o;
        o.x = h2u(__floats2half2_rn((float)(a0.x - 8) * s0, (float)(a0.y - 8) * s0));
        o.y = h2u(__floats2half2_rn((float)(a2.x - 8) * s0, (float)(a2.y - 8) * s0));
        o.z = h2u(__floats2half2_rn((float)(b0.x - 8) * s1, (float)(b0.y - 8) * s1));
        o.w = h2u(__floats2half2_rn((float)(b2.x - 8) * s1, (float)(b2.y - 8) * s1));
        *(uint4*)(g_B + (size_t)j * 4) = o;
    } else {
        int j = (bid - WBLOCKS) * 256 + threadIdx.x;   // < XCHUNKS
        int blk = j >> 11, c = j & 2047;
        int th = c & 31, it = (c >> 5) & 15, s = c >> 9;
        int mb = blk >> 6, kt = blk & 63;
        int row0 = (mb << 8) + (it << 4) + (th >> 2);
        int k0 = (kt << 6) + (s << 4) + ((th & 3) << 1);
        const float* x0 = x + ((size_t)row0 << 12) + k0;
        const float* x8 = x0 + (8 << 12);
        float ia0 = 1.0f / alpha[k0],     ia1 = 1.0f / alpha[k0 + 1];
        float ia8 = 1.0f / alpha[k0 + 8], ia9 = 1.0f / alpha[k0 + 9];
        float2 v00 = *(const float2*)(x0);
        float2 v10 = *(const float2*)(x8);
        float2 v08 = *(const float2*)(x0 + 8);
        float2 v18 = *(const float2*)(x8 + 8);
        uint4 o;
        o.x = h2u(__floats2half2_rn(v00.x * ia0, v00.y * ia1));
        o.y = h2u(__floats2half2_rn(v10.x * ia0, v10.y * ia1));
        o.z = h2u(__floats2half2_rn(v08.x * ia8, v08.y * ia9));
        o.w = h2u(__floats2half2_rn(v18.x * ia8, v18.y * ia9));
        *(uint4*)(g_A + (size_t)j * 4) = o;
    }
}

// ---------------- GEMM: 256x128 CTA, 8 warps (4x2) of 64x64 ----------------
__global__ __launch_bounds__(256, 1)
void awq_gemm_kernel(const float* __restrict__ bias, float* __restrict__ out) {
    extern __shared__ char sm[];
    const uint32_t sbase = smem_u32(sm);
    int tid = threadIdx.x, wid = tid >> 5, t = tid & 31;
    int wm = wid & 3, wn = wid >> 2;
    int mt = blockIdx.x, nt = blockIdx.y;

    const char* gA = (const char*)g_A + (size_t)mt * (NKT * A_KT_BYTES);
    const char* gB = (const char*)g_B + (size_t)nt * (NKT * B_KT_BYTES);

    const uint32_t cpoff = sbase + (uint32_t)tid * 16;
    auto copy_stage = [&](int kt, uint32_t pbase) {
        const char* srcA = gA + (size_t)kt * A_KT_BYTES + tid * 16;
#pragma unroll
        for (int r = 0; r < 8; r++)
            cp16(cpoff + pbase + r * 4096, srcA + r * 4096);
        const char* srcB = gB + (size_t)kt * B_KT_BYTES + tid * 16;
#pragma unroll
        for (int r = 0; r < 4; r++)
            cp16(cpoff + pbase + A_KT_BYTES + r * 4096, srcB + r * 4096);
    };

    copy_stage(0, 0); CP_COMMIT();
    copy_stage(1, STAGE_BYTES); CP_COMMIT();
    copy_stage(2, 2 * STAGE_BYTES); CP_COMMIT();

    float4 acc[4][8];
#pragma unroll
    for (int i = 0; i < 4; i++)
#pragma unroll
        for (int jj = 0; jj < 8; jj++) acc[i][jj] = make_float4(0.f, 0.f, 0.f, 0.f);

    const int aoff = wm * 2048 + t * 16;
    const int boff = A_KT_BYTES + wn * 2048 + t * 16;

    uint4 fa[2][4], fb[2][4];
    auto load_frag = [&](int bi, const char* stage, int s) {
        const char* ab = stage + s * 8192 + aoff;
        const char* bb = stage + s * 4096 + boff;
#pragma unroll
        for (int il = 0; il < 4; il++) fa[bi][il] = *(const uint4*)(ab + il * 512);
#pragma unroll
        for (int pl = 0; pl < 4; pl++) fb[bi][pl] = *(const uint4*)(bb + pl * 512);
    };
    auto do_mma = [&](int bi) {
#pragma unroll
        for (int il = 0; il < 4; il++)
#pragma unroll
            for (int jj = 0; jj < 8; jj++) {
                const uint4& bp = fb[bi][jj >> 1];
                if (jj & 1) mma_f16(acc[il][jj], fa[bi][il], bp.z, bp.w);
                else        mma_f16(acc[il][jj], fa[bi][il], bp.x, bp.y);
            }
    };

    // prologue: stages 0,1 arrived & visible; preload stage0 s0 frags
    CP_WAIT1();
    __syncthreads();
    load_frag(0, sm, 0);

    auto iter = [&](int kt, int p) {
        const char* stage = sm + (size_t)p * STAGE_BYTES;
        if (kt + 3 < NKT) copy_stage(kt + 3, (uint32_t)((p + 3) & 3) * STAGE_BYTES);
        CP_COMMIT();
#pragma unroll
        for (int s = 0; s < 4; s++) {
            int cur = s & 1;
            if (s < 3) load_frag(cur ^ 1, stage, s + 1);
            else if (kt + 1 < NKT)   // next stage's s0 (arrived & published)
                load_frag(cur ^ 1, sm + (size_t)((p + 1) & 3) * STAGE_BYTES, 0);
            do_mma(cur);
        }
        CP_WAIT1();          // stage kt+2 arrived
        __syncthreads();     // publish cross-thread; protect slot reuse
    };

    for (int kt = 0; kt < NKT; kt += 4) {
        iter(kt + 0, 0);
        iter(kt + 1, 1);
        iter(kt + 2, 2);
        iter(kt + 3, 3);
    }

    // ---- epilogue ----
    int quad = t >> 2, tq = t & 3;
    int row_base = mt * TM + wm * 64;
    int col_base = nt * TN + wn * 64;
#pragma unroll
    for (int il = 0; il < 4; il++) {
        int r0 = row_base + il * 16 + quad;
        float* o0 = out + (size_t)r0 * OUT_F;
        float* o1 = o0 + (size_t)8 * OUT_F;
#pragma unroll
        for (int jj = 0; jj < 8; jj++) {
            int cc = col_base + jj * 8 + tq * 2;
            float2 bv = *(const float2*)(bias + cc);
            float4 v = acc[il][jj];
            *(float2*)(o0 + cc) = make_float2(v.x + bv.x, v.y + bv.y);
            *(float2*)(o1 + cc) = make_float2(v.z + bv.x, v.w + bv.y);
        }
    }
}

// ---------------- launch ----------------
extern "C" void kernel_launch(void* const* d_in, const int* in_sizes, int n_in,
                              void* d_out, int out_size) {
    const float* x     = (const float*)d_in[0];
    const int*   qw    = (const int*)d_in[1];
    const float* sc    = (const float*)d_in[2];
    const float* alpha = (const float*)d_in[3];
    const float* bias  = (const float*)d_in[4];
    float* out = (float*)d_out;

    cudaFuncSetAttribute(awq_gemm_kernel,
                         cudaFuncAttributeMaxDynamicSharedMemorySize, SMEM_BYTES);

    prep_all_kernel<<<WBLOCKS + XBLOCKS, 256>>>(x, alpha, qw, sc);

    dim3 grid(MROWS / TM, OUT_F / TN);            // (16, 86)
    awq_gemm_kernel<<<grid, 256, SMEM_BYTES>>>(bias, out);
}

// round 12
// speedup vs baseline: 1.3107x; 1.0443x over previous
#include <cuda_runtime.h>
#include <cuda_fp16.h>
#include <cstdint>

// ============================================================
// AWQLinear via fp16 mma.sync m16n8k16 (same mantissa as tf32).
// y = (x/alpha) @ W_hat^T + bias, M=4096 N=11008 K=4096.
// R11 = R10 GEMM + tail-wave split: 1332 full 256x128 tiles
// (9 exact waves) + last 44 tiles split into 88 128x128 halves
// to shrink the partial-wave tail.
// ============================================================

#define IN_F   4096
#define OUT_F  11008
#define MROWS  4096
#define NKT    64
#define A_BLK_B32 8192
#define B_BLK_B32 4096
#define STAGE_BYTES ((A_BLK_B32 + B_BLK_B32) * 4)     // 48KB
#define SMEM_BYTES (4 * STAGE_BYTES)                  // 192KB
#define A_KT_BYTES (A_BLK_B32 * 4)
#define B_KT_BYTES (B_BLK_B32 * 4)

#define NTILES     1376          // 16 x 86
#define FULL_TILES 1332          // 9 waves x 148
#define SPLIT_TILES (NTILES - FULL_TILES)             // 44
#define GRID_CTAS  (FULL_TILES + 2 * SPLIT_TILES)     // 1420

#define XCHUNKS (MROWS * IN_F / 8)
#define WCHUNKS (OUT_F * IN_F / 8)
#define WBLOCKS (WCHUNKS / 256)                 // 22016
#define XBLOCKS (XCHUNKS / 256)                 // 8192

__device__ __half2 g_A[(size_t)XCHUNKS * 4];    // 32MB
__device__ __half2 g_B[(size_t)WCHUNKS * 4];    // 90MB

// ---------------- helpers ----------------
__device__ __forceinline__ uint32_t smem_u32(const void* p) {
    uint32_t a;
    asm("{ .reg .u64 t; cvta.to.shared.u64 t, %1; cvt.u32.u64 %0, t; }"
        : "=r"(a) : "l"(p));
    return a;
}
__device__ __forceinline__ void cp16(uint32_t dst, const void* src) {
    asm volatile("cp.async.cg.shared.global [%0], [%1], 16;"
                 :: "r"(dst), "l"(src) : "memory");
}
#define CP_COMMIT() asm volatile("cp.async.commit_group;" ::: "memory")
#define CP_WAIT1()  asm volatile("cp.async.wait_group 1;" ::: "memory")

__device__ __forceinline__ void mma_f16(float4& d, const uint4 a,
                                        const uint32_t b0, const uint32_t b1) {
    asm("mma.sync.aligned.m16n8k16.row.col.f32.f16.f16.f32 "
        "{%0,%1,%2,%3}, {%4,%5,%6,%7}, {%8,%9}, {%0,%1,%2,%3};"
        : "+f"(d.x), "+f"(d.y), "+f"(d.z), "+f"(d.w)
        : "r"(a.x), "r"(a.y), "r"(a.z), "r"(a.w), "r"(b0), "r"(b1));
}
__device__ __forceinline__ uint32_t h2u(__half2 h) { return *(uint32_t*)&h; }

// ---------------- merged prep: 1 thread = one 16B fragment chunk --------
__global__ void prep_all_kernel(const float* __restrict__ x,
                                const float* __restrict__ alpha,
                                const int* __restrict__ q,
                                const float* __restrict__ sc) {
    int bid = blockIdx.x;
    if (bid < WBLOCKS) {
        int j = bid * 256 + threadIdx.x;
        int blk = j >> 10, c = j & 1023;
        int th = c & 31, jp = (c >> 5) & 7, s = c >> 8;
        int nb = blk >> 6, kt = blk & 63;
        int o0 = (nb << 7) + (jp << 4) + (th >> 2);
        int k0 = (kt << 6) + (s << 4) + ((th & 3) << 1);
        int sblk = (kt << 1) + (s >> 1);
        const int* q0 = q + ((size_t)o0 << 12) + k0;
        const int* q8 = q0 + (8 << 12);
        float s0 = sc[(o0 << 7) + sblk];
        float s1 = sc[((o0 + 8) << 7) + sblk];
        int2 a0 = *(const int2*)(q0);
        int2 a2 = *(const int2*)(q0 + 8);
        int2 b0 = *(const int2*)(q8);
        int2 b2 = *(const int2*)(q8 + 8);
        uint4 o;
        o.x = h2u(__floats2half2_rn((float)(a0.x - 8) * s0, (float)(a0.y - 8) * s0));
        o.y = h2u(__floats2half2_rn((float)(a2.x - 8) * s0, (float)(a2.y - 8) * s0));
        o.z = h2u(__floats2half2_rn((float)(b0.x - 8) * s1, (float)(b0.y - 8) * s1));
        o.w = h2u(__floats2half2_rn((float)(b2.x - 8) * s1, (float)(b2.y - 8) * s1));
        *(uint4*)(g_B + (size_t)j * 4) = o;
    } else {
        int j = (bid - WBLOCKS) * 256 + threadIdx.x;
        int blk = j >> 11, c = j & 2047;
        int th = c & 31, it = (c >> 5) & 15, s = c >> 9;
        int mb = blk >> 6, kt = blk & 63;
        int row0 = (mb << 8) + (it << 4) + (th >> 2);
        int k0 = (kt << 6) + (s << 4) + ((th & 3) << 1);
        const float* x0 = x + ((size_t)row0 << 12) + k0;
        const float* x8 = x0 + (8 << 12);
        float ia0 = 1.0f / alpha[k0],     ia1 = 1.0f / alpha[k0 + 1];
        float ia8 = 1.0f / alpha[k0 + 8], ia9 = 1.0f / alpha[k0 + 9];
        float2 v00 = *(const float2*)(x0);
        float2 v10 = *(const float2*)(x8);
        float2 v08 = *(const float2*)(x0 + 8);
        float2 v18 = *(const float2*)(x8 + 8);
        uint4 o;
        o.x = h2u(__floats2half2_rn(v00.x * ia0, v00.y * ia1));
        o.y = h2u(__floats2half2_rn(v10.x * ia0, v10.y * ia1));
        o.z = h2u(__floats2half2_rn(v08.x * ia8, v08.y * ia9));
        o.w = h2u(__floats2half2_rn(v18.x * ia8, v18.y * ia9));
        *(uint4*)(g_A + (size_t)j * 4) = o;
    }
}

// ---------------- tile worker, NIL = A-itiles per warp (4 full / 2 half) ----
template<int NIL>
__device__ __forceinline__ void run_tile(int mt, int nt, int h, char* sm,
                                         uint32_t sbase,
                                         const float* __restrict__ bias,
                                         float* __restrict__ out) {
    int tid = threadIdx.x, wid = tid >> 5, t = tid & 31;
    int wm = wid & 3, wn = wid >> 2;
    const int itbase = (NIL == 4) ? (wm << 2) : (h * 8 + wm * 2);

    const char* gA = (const char*)g_A + (size_t)mt * (NKT * A_KT_BYTES);
    const char* gB = (const char*)g_B + (size_t)nt * (NKT * B_KT_BYTES);

    auto copy_stage = [&](int kt, uint32_t pbase) {
        const char* srcA = gA + (size_t)kt * A_KT_BYTES;
        if (NIL == 4) {
#pragma unroll
            for (int r = 0; r < 8; r++) {         // full 32KB A, linear
                uint32_t off = (uint32_t)(tid * 16 + r * 4096);
                cp16(sbase + pbase + off, srcA + off);
            }
        } else {
#pragma unroll
            for (int r = 0; r < 4; r++) {         // half: itiles h*8..h*8+7
                int idx = r * 256 + tid;          // 0..1023
                int s = idx >> 8, itl = h * 8 + ((idx >> 5) & 7), th = idx & 31;
                uint32_t off = (uint32_t)((((s << 4) + itl) << 9) + (th << 4));
                cp16(sbase + pbase + off, srcA + off);
            }
        }
        const char* srcB = gB + (size_t)kt * B_KT_BYTES;
#pragma unroll
        for (int r = 0; r < 4; r++) {             // 16KB B, linear
            uint32_t off = (uint32_t)(tid * 16 + r * 4096);
            cp16(sbase + pbase + A_KT_BYTES + off, srcB + off);
        }
    };

    copy_stage(0, 0); CP_COMMIT();
    copy_stage(1, STAGE_BYTES); CP_COMMIT();
    copy_stage(2, 2 * STAGE_BYTES); CP_COMMIT();

    float4 acc[NIL][8];
#pragma unroll
    for (int i = 0; i < NIL; i++)
#pragma unroll
        for (int jj = 0; jj < 8; jj++) acc[i][jj] = make_float4(0.f, 0.f, 0.f, 0.f);

    const int aoff = itbase * 512 + t * 16;
    const int boff = A_KT_BYTES + wn * 2048 + t * 16;

    uint4 fa[2][NIL], fb[2][4];
    auto load_frag = [&](int bi, const char* stage, int s) {
        const char* ab = stage + s * 8192 + aoff;
        const char* bb = stage + s * 4096 + boff;
#pragma unroll
        for (int il = 0; il < NIL; il++) fa[bi][il] = *(const uint4*)(ab + il * 512);
#pragma unroll
        for (int pl = 0; pl < 4; pl++) fb[bi][pl] = *(const uint4*)(bb + pl * 512);
    };
    auto do_mma = [&](int bi) {
#pragma unroll
        for (int il = 0; il < NIL; il++)
#pragma unroll
            for (int jj = 0; jj < 8; jj++) {
                const uint4& bp = fb[bi][jj >> 1];
                if (jj & 1) mma_f16(acc[il][jj], fa[bi][il], bp.z, bp.w);
                else        mma_f16(acc[il][jj], fa[bi][il], bp.x, bp.y);
            }
    };

    CP_WAIT1();
    __syncthreads();
    load_frag(0, sm, 0);

    auto iter = [&](int kt, int p) {
        const char* stage = sm + (size_t)p * STAGE_BYTES;
        if (kt + 3 < NKT) copy_stage(kt + 3, (uint32_t)((p + 3) & 3) * STAGE_BYTES);
        CP_COMMIT();
#pragma unroll
        for (int s = 0; s < 4; s++) {
            int cur = s & 1;
            if (s < 3) load_frag(cur ^ 1, stage, s + 1);
            else if (kt + 1 < NKT)
                load_frag(cur ^ 1, sm + (size_t)((p + 1) & 3) * STAGE_BYTES, 0);
            do_mma(cur);
        }
        CP_WAIT1();
        __syncthreads();
    };

    for (int kt = 0; kt < NKT; kt += 4) {
        iter(kt + 0, 0);
        iter(kt + 1, 1);
        iter(kt + 2, 2);
        iter(kt + 3, 3);
    }

    int quad = t >> 2, tq = t & 3;
    int col_base = nt * 128 + wn * 64;
#pragma unroll
    for (int il = 0; il < NIL; il++) {
        int r0 = mt * 256 + (itbase + il) * 16 + quad;
        float* o0 = out + (size_t)r0 * OUT_F;
        float* o1 = o0 + (size_t)8 * OUT_F;
#pragma unroll
        for (int jj = 0; jj < 8; jj++) {
            int cc = col_base + jj * 8 + tq * 2;
            float2 bv = *(const float2*)(bias + cc);
            float4 v = acc[il][jj];
            *(float2*)(o0 + cc) = make_float2(v.x + bv.x, v.y + bv.y);
            *(float2*)(o1 + cc) = make_float2(v.z + bv.x, v.w + bv.y);
        }
    }
}

// ---------------- GEMM entry: full tiles then split halves ----------------
__global__ __launch_bounds__(256, 1)
void awq_gemm_kernel(const float* __restrict__ bias, float* __restrict__ out) {
    extern __shared__ char sm[];
    const uint32_t sbase = smem_u32(sm);
    int bid = blockIdx.x;
    if (bid < FULL_TILES) {
        run_tile<4>(bid & 15, bid >> 4, 0, sm, sbase, bias, out);
    } else {
        int u = bid - FULL_TILES;
        int tle = FULL_TILES + (u >> 1);
        run_tile<2>(tle & 15, tle >> 4, u & 1, sm, sbase, bias, out);
    }
}

// ---------------- launch ----------------
extern "C" void kernel_launch(void* const* d_in, const int* in_sizes, int n_in,
                              void* d_out, int out_size) {
    const float* x     = (const float*)d_in[0];
    const int*   qw    = (const int*)d_in[1];
    const float* sc    = (const float*)d_in[2];
    const float* alpha = (const float*)d_in[3];
    const float* bias  = (const float*)d_in[4];
    float* out = (float*)d_out;

    cudaFuncSetAttribute(awq_gemm_kernel,
                         cudaFuncAttributeMaxDynamicSharedMemorySize, SMEM_BYTES);

    prep_all_kernel<<<WBLOCKS + XBLOCKS, 256>>>(x, alpha, qw, sc);

    awq_gemm_kernel<<<GRID_CTAS, 256, SMEM_BYTES>>>(bias, out);
}